// round 1
// baseline (speedup 1.0000x reference)
#include <cuda_runtime.h>
#include <math.h>

#define HWp 16384
#define Hdim 128
#define Wdim 128
#define Bn 8
#define Tn 10
#define Dn 10

// ---------------- scratch state (device globals: no allocation allowed) ----------------
__device__ float g_xx[(size_t)Bn*Tn*Dn*HWp];      // compounded input, 52.4 MB
__device__ float g_hs0[(size_t)Bn*Tn*HWp];        // enc L0 h states (+decoder ring)
__device__ float g_cs0[(size_t)Bn*Tn*HWp];
__device__ float g_hs1[(size_t)Bn*Tn*64*HWp];     // enc L1 h states (+decoder ring), 335 MB
__device__ float g_cs1[(size_t)Bn*Tn*64*HWp];     // 335 MB
__device__ float g_score[(size_t)Bn*Tn*HWp];      // attention scores (D or T = 10 slots)
__device__ float g_hid[(size_t)Bn*32*HWp];        // attention MLP hidden
__device__ float g_z[(size_t)Bn*256*HWp];         // conv gate output, 134 MB
__device__ float g_hatt[(size_t)Bn*64*HWp];       // temporal-attn weighted h

__device__ __forceinline__ float sigm(float x) { return 1.f / (1.f + __expf(-x)); }

// ---------------- generic 3x3 SAME conv, up to 3 strided input segments ----------------
// out[b, co, y, x] = bias[co] + sum_{cin,dy,dx} in[b, cin, y+dy-1, x+dx-1] * w[co, cin, dy, dx]
// Each block: 16x16 output tile, CB output channels; input tile + weights staged in smem.
template <int CB, int ACT>
__global__ void conv3x3_k(
    const float* __restrict__ in0, int n0, long c0s, long b0s,
    const float* __restrict__ in1, int n1, long c1s, long b1s,
    const float* __restrict__ in2, int n2, long c2s, long b2s,
    const float* __restrict__ wgt, const float* __restrict__ bias,
    float* __restrict__ out, int Cin, int Cout, long obs)
{
    __shared__ float tile[18 * 18];
    __shared__ float wsm[CB][9];

    int nCoBlk = gridDim.z / Bn;
    int b = blockIdx.z / nCoBlk;
    int cobase = (blockIdx.z % nCoBlk) * CB;
    int tid = threadIdx.x;
    int tx = tid & 15, ty = tid >> 4;
    int x0 = blockIdx.x * 16, y0 = blockIdx.y * 16;

    float acc[CB];
#pragma unroll
    for (int i = 0; i < CB; i++) acc[i] = 0.f;

    for (int cin = 0; cin < Cin; ++cin) {
        const float* src;
        if (cin < n0)            src = in0 + (long)b * b0s + (long)cin * c0s;
        else if (cin < n0 + n1)  src = in1 + (long)b * b1s + (long)(cin - n0) * c1s;
        else                     src = in2 + (long)b * b2s + (long)(cin - n0 - n1) * c2s;

        for (int i = tid; i < 18 * 18; i += 256) {
            int r = i / 18, c = i - r * 18;
            int gy = y0 + r - 1, gx = x0 + c - 1;
            float v = 0.f;
            if (gy >= 0 && gy < Hdim && gx >= 0 && gx < Wdim) v = src[gy * Wdim + gx];
            tile[i] = v;
        }
        if (tid < CB * 9) {
            int co = tid / 9, k = tid - co * 9;
            float wv = 0.f;
            if (cobase + co < Cout) wv = wgt[((long)(cobase + co) * Cin + cin) * 9 + k];
            wsm[co][k] = wv;
        }
        __syncthreads();

        float v[9];
#pragma unroll
        for (int dy = 0; dy < 3; dy++)
#pragma unroll
            for (int dx = 0; dx < 3; dx++)
                v[dy * 3 + dx] = tile[(ty + dy) * 18 + tx + dx];
#pragma unroll
        for (int co = 0; co < CB; co++) {
            float a = acc[co];
#pragma unroll
            for (int k = 0; k < 9; k++) a = fmaf(v[k], wsm[co][k], a);
            acc[co] = a;
        }
        __syncthreads();
    }

    int oy = y0 + ty, ox = x0 + tx;
#pragma unroll
    for (int co = 0; co < CB; co++) {
        int c = cobase + co;
        if (c < Cout) {
            float r = acc[co] + bias[c];
            if (ACT == 1) r = tanhf(r);
            out[(long)b * obs + (long)c * HWp + oy * Wdim + ox] = r;
        }
    }
}

// ---------------- LSTM pointwise gate update ----------------
__global__ void lstm_k(const float* __restrict__ z, const float* __restrict__ cin, long cin_bs,
                       float* __restrict__ hout, long h_bs, float* __restrict__ cout_, long c_bs,
                       float* __restrict__ hout2, long h2_bs, int C)
{
    long total = (long)Bn * C * HWp;
    long idx = (long)blockIdx.x * blockDim.x + threadIdx.x;
    if (idx >= total) return;
    long CHW = (long)C * HWp;
    int b = (int)(idx / CHW);
    long r = idx - (long)b * CHW;
    const float* zb = z + (long)b * 4 * CHW;
    float zi = zb[r], zf = zb[CHW + r], zo = zb[2 * CHW + r], zg = zb[3 * CHW + r];
    float c = cin[(long)b * cin_bs + r];
    float c2 = sigm(zf) * c + sigm(zi) * tanhf(zg);
    float h2 = sigm(zo) * tanhf(c2);
    hout[(long)b * h_bs + r] = h2;
    cout_[(long)b * c_bs + r] = c2;
    if (hout2) hout2[(long)b * h2_bs + r] = h2;
}

// ---------------- input attention: softmax over D, compounding reweight of xx ----------------
__global__ void inattn_k(const float* __restrict__ score, float* __restrict__ xx)
{
    int idx = blockIdx.x * blockDim.x + threadIdx.x;
    if (idx >= Bn * HWp) return;
    int b = idx / HWp, p = idx - b * HWp;
    const float* sc = score + (long)b * Dn * HWp + p;
    float s[Dn];
    float m = -1e30f;
#pragma unroll
    for (int k = 0; k < Dn; k++) { s[k] = sc[(long)k * HWp]; m = fmaxf(m, s[k]); }
    float sum = 0.f;
#pragma unroll
    for (int k = 0; k < Dn; k++) { s[k] = __expf(s[k] - m); sum += s[k]; }
    float inv = 1.f / sum;
    float* xb = xx + (long)b * Tn * Dn * HWp + p;
#pragma unroll
    for (int k = 0; k < Dn; k++) {
        float a = s[k] * inv;
        for (int t = 0; t < Tn; t++) xb[((long)t * Dn + k) * HWp] *= a;
    }
}

// ---------------- temporal attention: softmax over T + weighted sum of ring-buffered hs1 ----------------
__global__ void tattn_k(const float* __restrict__ score, const float* __restrict__ hs1,
                        float* __restrict__ hatt, int s)
{
    int idx = blockIdx.x * blockDim.x + threadIdx.x;
    if (idx >= Bn * HWp) return;
    int b = idx / HWp, p = idx - b * HWp;
    const float* sc = score + (long)b * Tn * HWp + p;
    float bt[Tn];
    float m = -1e30f;
#pragma unroll
    for (int t = 0; t < Tn; t++) { bt[t] = sc[(long)t * HWp]; m = fmaxf(m, bt[t]); }
    float sum = 0.f;
#pragma unroll
    for (int t = 0; t < Tn; t++) { bt[t] = __expf(bt[t] - m); sum += bt[t]; }
    float inv = 1.f / sum;
    float acc[64];
#pragma unroll
    for (int c = 0; c < 64; c++) acc[c] = 0.f;
    for (int t = 0; t < Tn; t++) {
        int phys = (s + t) % Tn;
        const float* hb = hs1 + ((long)b * Tn + phys) * 64 * HWp + p;
        float w = bt[t] * inv;
#pragma unroll
        for (int c = 0; c < 64; c++) acc[c] = fmaf(hb[(long)c * HWp], w, acc[c]);
    }
    float* ob = hatt + (long)b * 64 * HWp + p;
#pragma unroll
    for (int c = 0; c < 64; c++) ob[(long)c * HWp] = acc[c];
}

// ---------------- host side ----------------
struct Seg { const float* p; int n; long cs; long bs; };
static inline Seg mkseg(const float* p, int n, long cs, long bs) { Seg s; s.p = p; s.n = n; s.cs = cs; s.bs = bs; return s; }

static void conv3x3(int CB, int ACT, Seg a, Seg b, Seg c,
                    const float* w, const float* bias, float* out,
                    int Cin, int Cout, long obs)
{
    dim3 grid(Wdim / 16, Hdim / 16, Bn * ((Cout + CB - 1) / CB));
#define CARGS a.p, a.n, a.cs, a.bs, b.p, b.n, b.cs, b.bs, c.p, c.n, c.cs, c.bs, w, bias, out, Cin, Cout, obs
    if (CB == 8 && ACT == 1)      conv3x3_k<8, 1><<<grid, 256>>>(CARGS);
    else if (CB == 8)             conv3x3_k<8, 0><<<grid, 256>>>(CARGS);
    else if (CB == 4)             conv3x3_k<4, 0><<<grid, 256>>>(CARGS);
    else                          conv3x3_k<1, 0><<<grid, 256>>>(CARGS);
#undef CARGS
}

extern "C" void kernel_launch(void* const* d_in, const int* in_sizes, int n_in,
                              void* d_out, int out_size)
{
    const float* x      = (const float*)d_in[0];
    const float* h0     = (const float*)d_in[1];
    const float* c0     = (const float*)d_in[2];
    const float* h1     = (const float*)d_in[3];
    const float* c1     = (const float*)d_in[4];
    const float* w_enc0 = (const float*)d_in[5];
    const float* b_enc0 = (const float*)d_in[6];
    const float* w_enc1 = (const float*)d_in[7];
    const float* b_enc1 = (const float*)d_in[8];
    const float* w_dec0 = (const float*)d_in[9];
    const float* b_dec0 = (const float*)d_in[10];
    const float* w_dec1 = (const float*)d_in[11];
    const float* b_dec1 = (const float*)d_in[12];
    const float* wa1    = (const float*)d_in[13];
    const float* ba1    = (const float*)d_in[14];
    const float* wa2    = (const float*)d_in[15];
    const float* ba2    = (const float*)d_in[16];
    const float* wt1    = (const float*)d_in[17];
    const float* bt1    = (const float*)d_in[18];
    const float* wt2    = (const float*)d_in[19];
    const float* bt2    = (const float*)d_in[20];

    float *xx, *hs0, *cs0, *hs1, *cs1, *score, *hid, *z, *hatt;
    cudaGetSymbolAddress((void**)&xx, g_xx);
    cudaGetSymbolAddress((void**)&hs0, g_hs0);
    cudaGetSymbolAddress((void**)&cs0, g_cs0);
    cudaGetSymbolAddress((void**)&hs1, g_hs1);
    cudaGetSymbolAddress((void**)&cs1, g_cs1);
    cudaGetSymbolAddress((void**)&score, g_score);
    cudaGetSymbolAddress((void**)&hid, g_hid);
    cudaGetSymbolAddress((void**)&z, g_z);
    cudaGetSymbolAddress((void**)&hatt, g_hatt);

    // xx = x (compounding attention re-weights it in place)
    cudaMemcpyAsync(xx, x, sizeof(float) * (size_t)Bn * Tn * Dn * HWp,
                    cudaMemcpyDeviceToDevice);

    Seg none = mkseg(nullptr, 0, 0, 0);
    const int thr = 256;

    // ======== encoder layer 0 (hidden 1) with compounding input attention ========
    for (int t = 0; t < Tn; t++) {
        const float* hp = (t == 0) ? h0 : hs0 + (long)(t - 1) * HWp;
        long hbs        = (t == 0) ? (long)HWp : (long)Tn * HWp;
        const float* cp = (t == 0) ? c0 : cs0 + (long)(t - 1) * HWp;
        long cbs = hbs;

        for (int k = 0; k < Dn; k++) {
            // attn conv1: channels = [T time-slices of feature k (10), h (1), c (1)] = 12
            conv3x3(8, 1,
                    mkseg(xx + (long)k * HWp, Tn, (long)Dn * HWp, (long)Tn * Dn * HWp),
                    mkseg(hp, 1, HWp, hbs),
                    mkseg(cp, 1, HWp, cbs),
                    wa1, ba1, hid, 12, 32, 32L * HWp);
            // attn conv2: 32 -> 1, write score slice k
            conv3x3(1, 0,
                    mkseg(hid, 32, HWp, 32L * HWp), none, none,
                    wa2, ba2, score + (long)k * HWp, 32, 1, (long)Dn * HWp);
        }
        inattn_k<<<(Bn * HWp + thr - 1) / thr, thr>>>(score, xx);

        // enc0 gate conv: [xx[:,t] (10), h (1)] = 11 -> 4
        conv3x3(4, 0,
                mkseg(xx + (long)t * Dn * HWp, Dn, (long)HWp, (long)Tn * Dn * HWp),
                mkseg(hp, 1, HWp, hbs), none,
                w_enc0, b_enc0, z, 11, 4, 4L * HWp);
        long n = (long)Bn * HWp;
        lstm_k<<<(n + thr - 1) / thr, thr>>>(z, cp, cbs,
                                             hs0 + (long)t * HWp, (long)Tn * HWp,
                                             cs0 + (long)t * HWp, (long)Tn * HWp,
                                             nullptr, 0, 1);
    }

    // ======== encoder layer 1 (hidden 64) ========
    for (int t = 0; t < Tn; t++) {
        const float* hp = (t == 0) ? h1 : hs1 + (long)(t - 1) * 64 * HWp;
        long hbs        = (t == 0) ? 64L * HWp : (long)Tn * 64 * HWp;
        const float* cp = (t == 0) ? c1 : cs1 + (long)(t - 1) * 64 * HWp;

        conv3x3(8, 0,
                mkseg(hs0 + (long)t * HWp, 1, HWp, (long)Tn * HWp),
                mkseg(hp, 64, HWp, hbs), none,
                w_enc1, b_enc1, z, 65, 256, 256L * HWp);
        long n = (long)Bn * 64 * HWp;
        lstm_k<<<(n + thr - 1) / thr, thr>>>(z, cp, hbs,
                                             hs1 + (long)t * 64 * HWp, (long)Tn * 64 * HWp,
                                             cs1 + (long)t * 64 * HWp, (long)Tn * 64 * HWp,
                                             nullptr, 0, 64);
    }

    // ======== decoder, 5 steps; ring buffers via modular slot indexing ========
    float* out = (float*)d_out;
    for (int s = 0; s < 5; s++) {
        const float* yp; long ybs;
        if (s == 0) { yp = x + 90L * HWp; ybs = 100L * HWp; }               // x[:, -1, 0]
        else        { yp = hs0 + (long)(s - 1) * HWp; ybs = (long)Tn * HWp; } // prev step's y

        // temporal attention scores over all T ring slots
        for (int t = 0; t < Tn; t++) {
            int phys = (s + t) % Tn;
            conv3x3(8, 1,
                    mkseg(yp, 1, HWp, ybs),
                    mkseg(hs1 + (long)phys * 64 * HWp, 64, HWp, (long)Tn * 64 * HWp),
                    mkseg(cs1 + (long)phys * 64 * HWp, 64, HWp, (long)Tn * 64 * HWp),
                    wt1, bt1, hid, 129, 32, 32L * HWp);
            conv3x3(1, 0,
                    mkseg(hid, 32, HWp, 32L * HWp), none, none,
                    wt2, bt2, score + (long)t * HWp, 32, 1, (long)Tn * HWp);
        }
        tattn_k<<<(Bn * HWp + thr - 1) / thr, thr>>>(score, hs1, hatt, s);

        int pl = (s + 9) % Tn;  // logical last slot

        // decoder L0: conv [y (1), hatt (64)] -> 256; c_in = cs1 last slot
        conv3x3(8, 0,
                mkseg(yp, 1, HWp, ybs),
                mkseg(hatt, 64, HWp, 64L * HWp), none,
                w_dec0, b_dec0, z, 65, 256, 256L * HWp);
        long n64 = (long)Bn * 64 * HWp;
        lstm_k<<<(n64 + thr - 1) / thr, thr>>>(z, cs1 + (long)pl * 64 * HWp, (long)Tn * 64 * HWp,
                                               hs1 + (long)s * 64 * HWp, (long)Tn * 64 * HWp,
                                               cs1 + (long)s * 64 * HWp, (long)Tn * 64 * HWp,
                                               nullptr, 0, 64);

        // decoder L1: conv [y64 = new ht (64), hs0 last slot (1)] -> 4
        conv3x3(4, 0,
                mkseg(hs1 + (long)s * 64 * HWp, 64, HWp, (long)Tn * 64 * HWp),
                mkseg(hs0 + (long)pl * HWp, 1, HWp, (long)Tn * HWp), none,
                w_dec1, b_dec1, z, 65, 4, 4L * HWp);
        long n1 = (long)Bn * HWp;
        lstm_k<<<(n1 + thr - 1) / thr, thr>>>(z, cs0 + (long)pl * HWp, (long)Tn * HWp,
                                              hs0 + (long)s * HWp, (long)Tn * HWp,
                                              cs0 + (long)s * HWp, (long)Tn * HWp,
                                              out + (long)s * HWp, 5L * HWp, 1);
    }
}

// round 2
// speedup vs baseline: 3.7830x; 3.7830x over previous
#include <cuda_runtime.h>
#include <math.h>

#define HWp 16384
#define Hdim 128
#define Wdim 128
#define Bn 8
#define Tn 10
#define Dn 10

// ---------------- scratch state (device globals) ----------------
__device__ float g_xx[(size_t)Bn*Tn*Dn*HWp];        // compounded input
__device__ float g_hs0[(size_t)Bn*Tn*HWp];
__device__ float g_cs0[(size_t)Bn*Tn*HWp];
__device__ float g_hs1[(size_t)Bn*Tn*64*HWp];
__device__ float g_cs1[(size_t)Bn*Tn*64*HWp];
__device__ float g_score[(size_t)Bn*Tn*HWp];
__device__ float g_hid[(size_t)Tn*Bn*32*HWp];       // attn hidden, replicated over k/t
__device__ float g_z[(size_t)Bn*256*HWp];
__device__ float g_hatt[(size_t)Bn*64*HWp];
__device__ float g_tc[(size_t)Tn*Bn*32*HWp];        // cached conv_hc(h,c)+bt1 per ring slot

__device__ __forceinline__ float sigm(float x) { return 1.f / (1.f + __expf(-x)); }

// ---------------- generic 3x3 SAME conv ----------------
// 32x32 output tile per block, 2x2 pixels/thread, CB output channels.
// Up to 3 strided input segments; optional residual-add (ring-indexed) and tanh.
template <int CB, int ACT>
__global__ void __launch_bounds__(256) convk(
    const float* __restrict__ in0, int n0, long c0s, long b0s, long r0s,
    const float* __restrict__ in1, int n1, long c1s, long b1s, long r1s,
    const float* __restrict__ in2, int n2, long c2s, long b2s, long r2s,
    const float* __restrict__ wgt, int Cw,
    const float* __restrict__ bias,
    const float* __restrict__ radd, long radd_rs, long radd_bs, int ring_s,
    float* __restrict__ out, long o_rs, long obs,
    int Cin, int Cout, int nCo)
{
    __shared__ float tile[2][34 * 34];
    __shared__ float wsm[2][CB][9];

    int z = blockIdx.z;
    int cb = z % nCo;
    int zb = z / nCo;
    int b = zb % Bn;
    int r = zb / Bn;
    int cobase = cb * CB;

    int tid = threadIdx.x;
    int txc = tid & 15, tyr = tid >> 4;
    int x0 = blockIdx.x * 32, y0 = blockIdx.y * 32;

    // precompute halo-tile load offsets (5 stripes of 256)
    int goff[5]; bool gok[5];
#pragma unroll
    for (int j = 0; j < 5; j++) {
        int i = tid + j * 256;
        int rr = i / 34, cc = i - rr * 34;
        int gy = y0 + rr - 1, gx = x0 + cc - 1;
        gok[j] = (i < 34 * 34) && (gy >= 0) && (gy < Hdim) && (gx >= 0) && (gx < Wdim);
        goff[j] = gy * Wdim + gx;
    }
    bool wldr = tid < CB * 9;
    int wco = tid / 9, wk = tid - wco * 9;
    bool wok = wldr && (cobase + wco < Cout);
    long wbase = ((long)(cobase + wco) * Cw) * 9 + wk;

    float acc[CB][4];
#pragma unroll
    for (int co = 0; co < CB; co++)
#pragma unroll
        for (int q = 0; q < 4; q++) acc[co][q] = 0.f;

    auto load_cin = [&](int cin, int p) {
        const float* src;
        if (cin < n0)           src = in0 + (long)b * b0s + (long)r * r0s + (long)cin * c0s;
        else if (cin < n0 + n1) src = in1 + (long)b * b1s + (long)r * r1s + (long)(cin - n0) * c1s;
        else                    src = in2 + (long)b * b2s + (long)r * r2s + (long)(cin - n0 - n1) * c2s;
#pragma unroll
        for (int j = 0; j < 4; j++)
            tile[p][tid + j * 256] = gok[j] ? src[goff[j]] : 0.f;
        if (tid + 1024 < 34 * 34)
            tile[p][tid + 1024] = gok[4] ? src[goff[4]] : 0.f;
        if (wldr)
            wsm[p][wco][wk] = wok ? wgt[wbase + (long)cin * 9] : 0.f;
    };

    load_cin(0, 0);
    __syncthreads();

    for (int cin = 0; cin < Cin; cin++) {
        int p = cin & 1;
        if (cin + 1 < Cin) load_cin(cin + 1, p ^ 1);

        float v[4][4];
#pragma unroll
        for (int rr = 0; rr < 4; rr++)
#pragma unroll
            for (int cc = 0; cc < 4; cc++)
                v[rr][cc] = tile[p][(2 * tyr + rr) * 34 + 2 * txc + cc];

#pragma unroll
        for (int co = 0; co < CB; co++) {
#pragma unroll
            for (int k = 0; k < 9; k++) {
                float w = wsm[p][co][k];
                int dy = k / 3, dx = k % 3;
                acc[co][0] = fmaf(v[dy][dx],         w, acc[co][0]);
                acc[co][1] = fmaf(v[dy][dx + 1],     w, acc[co][1]);
                acc[co][2] = fmaf(v[dy + 1][dx],     w, acc[co][2]);
                acc[co][3] = fmaf(v[dy + 1][dx + 1], w, acc[co][3]);
            }
        }
        __syncthreads();
    }

    int ox = x0 + 2 * txc, oy = y0 + 2 * tyr;
    long p0 = (long)oy * Wdim + ox;
    int pr = (radd && ring_s >= 0) ? (ring_s + r) % Tn : r;
#pragma unroll
    for (int co = 0; co < CB; co++) {
        int c = cobase + co;
        if (c >= Cout) continue;
        float bs = bias ? bias[c] : 0.f;
        float v0 = acc[co][0] + bs, v1 = acc[co][1] + bs;
        float v2 = acc[co][2] + bs, v3 = acc[co][3] + bs;
        if (radd) {
            const float* ra = radd + (long)pr * radd_rs + (long)b * radd_bs + (long)c * HWp + p0;
            v0 += ra[0]; v1 += ra[1]; v2 += ra[Wdim]; v3 += ra[Wdim + 1];
        }
        if (ACT == 1) { v0 = tanhf(v0); v1 = tanhf(v1); v2 = tanhf(v2); v3 = tanhf(v3); }
        float* o = out + (long)r * o_rs + (long)b * obs + (long)c * HWp + p0;
        o[0] = v0; o[1] = v1; o[Wdim] = v2; o[Wdim + 1] = v3;
    }
}

// ---------------- LSTM pointwise gate update ----------------
__global__ void lstm_k(const float* __restrict__ z, const float* __restrict__ cin, long cin_bs,
                       float* __restrict__ hout, long h_bs, float* __restrict__ cout_, long c_bs,
                       float* __restrict__ hout2, long h2_bs, int C)
{
    long total = (long)Bn * C * HWp;
    long idx = (long)blockIdx.x * blockDim.x + threadIdx.x;
    if (idx >= total) return;
    long CHW = (long)C * HWp;
    int b = (int)(idx / CHW);
    long r = idx - (long)b * CHW;
    const float* zb = z + (long)b * 4 * CHW;
    float zi = zb[r], zf = zb[CHW + r], zo = zb[2 * CHW + r], zg = zb[3 * CHW + r];
    float c = cin[(long)b * cin_bs + r];
    float c2 = sigm(zf) * c + sigm(zi) * tanhf(zg);
    float h2 = sigm(zo) * tanhf(c2);
    hout[(long)b * h_bs + r] = h2;
    cout_[(long)b * c_bs + r] = c2;
    if (hout2) hout2[(long)b * h2_bs + r] = h2;
}

// ---------------- input attention softmax + compounding reweight ----------------
__global__ void inattn_k(const float* __restrict__ score, float* __restrict__ xx)
{
    int idx = blockIdx.x * blockDim.x + threadIdx.x;
    if (idx >= Bn * HWp) return;
    int b = idx / HWp, p = idx - b * HWp;
    const float* sc = score + (long)b * Dn * HWp + p;
    float s[Dn];
    float m = -1e30f;
#pragma unroll
    for (int k = 0; k < Dn; k++) { s[k] = sc[(long)k * HWp]; m = fmaxf(m, s[k]); }
    float sum = 0.f;
#pragma unroll
    for (int k = 0; k < Dn; k++) { s[k] = __expf(s[k] - m); sum += s[k]; }
    float inv = 1.f / sum;
    float* xb = xx + (long)b * Tn * Dn * HWp + p;
#pragma unroll
    for (int k = 0; k < Dn; k++) {
        float a = s[k] * inv;
        for (int t = 0; t < Tn; t++) xb[((long)t * Dn + k) * HWp] *= a;
    }
}

// ---------------- temporal attention softmax + weighted sum ----------------
__global__ void tattn_k(const float* __restrict__ score, const float* __restrict__ hs1,
                        float* __restrict__ hatt, int s)
{
    int idx = blockIdx.x * blockDim.x + threadIdx.x;
    if (idx >= Bn * HWp) return;
    int b = idx / HWp, p = idx - b * HWp;
    const float* sc = score + (long)b * Tn * HWp + p;
    float bt[Tn];
    float m = -1e30f;
#pragma unroll
    for (int t = 0; t < Tn; t++) { bt[t] = sc[(long)t * HWp]; m = fmaxf(m, bt[t]); }
    float sum = 0.f;
#pragma unroll
    for (int t = 0; t < Tn; t++) { bt[t] = __expf(bt[t] - m); sum += bt[t]; }
    float inv = 1.f / sum;
    float acc[64];
#pragma unroll
    for (int c = 0; c < 64; c++) acc[c] = 0.f;
    for (int t = 0; t < Tn; t++) {
        int phys = (s + t) % Tn;
        const float* hb = hs1 + ((long)b * Tn + phys) * 64 * HWp + p;
        float w = bt[t] * inv;
#pragma unroll
        for (int c = 0; c < 64; c++) acc[c] = fmaf(hb[(long)c * HWp], w, acc[c]);
    }
    float* ob = hatt + (long)b * 64 * HWp + p;
#pragma unroll
    for (int c = 0; c < 64; c++) ob[(long)c * HWp] = acc[c];
}

// ---------------- host side ----------------
struct Seg { const float* p; int n; long cs, bs, rs; };
static inline Seg mkseg(const float* p, int n, long cs, long bs, long rs) {
    Seg s; s.p = p; s.n = n; s.cs = cs; s.bs = bs; s.rs = rs; return s;
}

static void conv(int CB, int ACT, Seg a, Seg b, Seg c,
                 const float* w, int Cw, const float* bias,
                 const float* radd, long rrs, long rbs, int ring_s,
                 float* out, long ors, long obs, int Cin, int Cout, int R)
{
    int nCo = (Cout + CB - 1) / CB;
    dim3 grid(Wdim / 32, Hdim / 32, R * Bn * nCo);
#define CARGS a.p, a.n, a.cs, a.bs, a.rs, b.p, b.n, b.cs, b.bs, b.rs, c.p, c.n, c.cs, c.bs, c.rs, \
              w, Cw, bias, radd, rrs, rbs, ring_s, out, ors, obs, Cin, Cout, nCo
    if (CB == 16)                 convk<16, 0><<<grid, 256>>>(CARGS);
    else if (CB == 8 && ACT == 1) convk<8, 1><<<grid, 256>>>(CARGS);
    else if (CB == 8)             convk<8, 0><<<grid, 256>>>(CARGS);
    else if (CB == 4)             convk<4, 0><<<grid, 256>>>(CARGS);
    else                          convk<1, 0><<<grid, 256>>>(CARGS);
#undef CARGS
}

extern "C" void kernel_launch(void* const* d_in, const int* in_sizes, int n_in,
                              void* d_out, int out_size)
{
    const float* x      = (const float*)d_in[0];
    const float* h0     = (const float*)d_in[1];
    const float* c0     = (const float*)d_in[2];
    const float* h1     = (const float*)d_in[3];
    const float* c1     = (const float*)d_in[4];
    const float* w_enc0 = (const float*)d_in[5];
    const float* b_enc0 = (const float*)d_in[6];
    const float* w_enc1 = (const float*)d_in[7];
    const float* b_enc1 = (const float*)d_in[8];
    const float* w_dec0 = (const float*)d_in[9];
    const float* b_dec0 = (const float*)d_in[10];
    const float* w_dec1 = (const float*)d_in[11];
    const float* b_dec1 = (const float*)d_in[12];
    const float* wa1    = (const float*)d_in[13];
    const float* ba1    = (const float*)d_in[14];
    const float* wa2    = (const float*)d_in[15];
    const float* ba2    = (const float*)d_in[16];
    const float* wt1    = (const float*)d_in[17];
    const float* bt1    = (const float*)d_in[18];
    const float* wt2    = (const float*)d_in[19];
    const float* bt2    = (const float*)d_in[20];

    float *xx, *hs0, *cs0, *hs1, *cs1, *score, *hid, *z, *hatt, *tc;
    cudaGetSymbolAddress((void**)&xx, g_xx);
    cudaGetSymbolAddress((void**)&hs0, g_hs0);
    cudaGetSymbolAddress((void**)&cs0, g_cs0);
    cudaGetSymbolAddress((void**)&hs1, g_hs1);
    cudaGetSymbolAddress((void**)&cs1, g_cs1);
    cudaGetSymbolAddress((void**)&score, g_score);
    cudaGetSymbolAddress((void**)&hid, g_hid);
    cudaGetSymbolAddress((void**)&z, g_z);
    cudaGetSymbolAddress((void**)&hatt, g_hatt);
    cudaGetSymbolAddress((void**)&tc, g_tc);

    cudaMemcpyAsync(xx, x, sizeof(float) * (size_t)Bn * Tn * Dn * HWp,
                    cudaMemcpyDeviceToDevice);

    Seg none = mkseg(nullptr, 0, 0, 0, 0);
    const int thr = 256;
    const long HID_RS = (long)Bn * 32 * HWp;

    // ======== encoder layer 0 (hidden 1), compounding input attention ========
    for (int t = 0; t < Tn; t++) {
        const float* hp = (t == 0) ? h0 : hs0 + (long)(t - 1) * HWp;
        long hbs        = (t == 0) ? (long)HWp : (long)Tn * HWp;
        const float* cp = (t == 0) ? c0 : cs0 + (long)(t - 1) * HWp;
        long cbs = hbs;

        // attn conv1 for ALL D features in one launch (R = feature k)
        conv(8, 1,
             mkseg(xx, Tn, (long)Dn * HWp, (long)Tn * Dn * HWp, (long)HWp),
             mkseg(hp, 1, 0, hbs, 0),
             mkseg(cp, 1, 0, cbs, 0),
             wa1, 12, ba1, nullptr, 0, 0, -1,
             hid, HID_RS, 32L * HWp, 12, 32, Dn);
        // attn conv2 for all features
        conv(1, 0,
             mkseg(hid, 32, HWp, 32L * HWp, HID_RS), none, none,
             wa2, 32, ba2, nullptr, 0, 0, -1,
             score, (long)HWp, (long)Dn * HWp, 32, 1, Dn);
        inattn_k<<<(Bn * HWp + thr - 1) / thr, thr>>>(score, xx);

        // enc0 gate conv: [xx[:,t] (10), h (1)] -> 4
        conv(4, 0,
             mkseg(xx + (long)t * Dn * HWp, Dn, (long)HWp, (long)Tn * Dn * HWp, 0),
             mkseg(hp, 1, 0, hbs, 0), none,
             w_enc0, 11, b_enc0, nullptr, 0, 0, -1,
             z, 0, 4L * HWp, 11, 4, 1);
        long n = (long)Bn * HWp;
        lstm_k<<<(n + thr - 1) / thr, thr>>>(z, cp, cbs,
                                             hs0 + (long)t * HWp, (long)Tn * HWp,
                                             cs0 + (long)t * HWp, (long)Tn * HWp,
                                             nullptr, 0, 1);
    }

    // ======== encoder layer 1 (hidden 64) ========
    for (int t = 0; t < Tn; t++) {
        const float* hp = (t == 0) ? h1 : hs1 + (long)(t - 1) * 64 * HWp;
        long hbs        = (t == 0) ? 64L * HWp : (long)Tn * 64 * HWp;
        const float* cp = (t == 0) ? c1 : cs1 + (long)(t - 1) * 64 * HWp;

        conv(16, 0,
             mkseg(hs0 + (long)t * HWp, 1, 0, (long)Tn * HWp, 0),
             mkseg(hp, 64, HWp, hbs, 0), none,
             w_enc1, 65, b_enc1, nullptr, 0, 0, -1,
             z, 0, 256L * HWp, 65, 256, 1);
        long n = (long)Bn * 64 * HWp;
        lstm_k<<<(n + thr - 1) / thr, thr>>>(z, cp, hbs,
                                             hs1 + (long)t * 64 * HWp, (long)Tn * 64 * HWp,
                                             cs1 + (long)t * 64 * HWp, (long)Tn * 64 * HWp,
                                             nullptr, 0, 64);
    }

    // ======== temporal-attn h/c conv cache for all 10 slots ========
    conv(8, 0,
         mkseg(hs1, 64, HWp, (long)Tn * 64 * HWp, 64L * HWp),
         mkseg(cs1, 64, HWp, (long)Tn * 64 * HWp, 64L * HWp), none,
         wt1 + 9, 129, bt1, nullptr, 0, 0, -1,
         tc, HID_RS, 32L * HWp, 128, 32, Tn);

    // ======== decoder ========
    float* out = (float*)d_out;
    for (int s = 0; s < 5; s++) {
        const float* yp; long ybs;
        if (s == 0) { yp = x + 90L * HWp; ybs = 100L * HWp; }
        else        { yp = hs0 + (long)(s - 1) * HWp; ybs = (long)Tn * HWp; }

        // hid[t] = tanh(conv_y(y) + tc[(s+t)%10])   for all 10 slots, one launch
        conv(8, 1,
             mkseg(yp, 1, 0, ybs, 0), none, none,
             wt1, 129, nullptr, tc, HID_RS, 32L * HWp, s,
             hid, HID_RS, 32L * HWp, 1, 32, Tn);
        // conv2 -> score[b][t]
        conv(1, 0,
             mkseg(hid, 32, HWp, 32L * HWp, HID_RS), none, none,
             wt2, 32, bt2, nullptr, 0, 0, -1,
             score, (long)HWp, (long)Tn * HWp, 32, 1, Tn);
        tattn_k<<<(Bn * HWp + thr - 1) / thr, thr>>>(score, hs1, hatt, s);

        int pl = (s + 9) % Tn;

        // decoder L0: conv [y (1), hatt (64)] -> 256
        conv(16, 0,
             mkseg(yp, 1, 0, ybs, 0),
             mkseg(hatt, 64, HWp, 64L * HWp, 0), none,
             w_dec0, 65, b_dec0, nullptr, 0, 0, -1,
             z, 0, 256L * HWp, 65, 256, 1);
        long n64 = (long)Bn * 64 * HWp;
        lstm_k<<<(n64 + thr - 1) / thr, thr>>>(z, cs1 + (long)pl * 64 * HWp, (long)Tn * 64 * HWp,
                                               hs1 + (long)s * 64 * HWp, (long)Tn * 64 * HWp,
                                               cs1 + (long)s * 64 * HWp, (long)Tn * 64 * HWp,
                                               nullptr, 0, 64);

        // refresh tc cache for the newly written slot s
        conv(8, 0,
             mkseg(hs1 + (long)s * 64 * HWp, 64, HWp, (long)Tn * 64 * HWp, 0),
             mkseg(cs1 + (long)s * 64 * HWp, 64, HWp, (long)Tn * 64 * HWp, 0), none,
             wt1 + 9, 129, bt1, nullptr, 0, 0, -1,
             tc + (long)s * HID_RS, 0, 32L * HWp, 128, 32, 1);

        // decoder L1: conv [y64 (64), hs0 last (1)] -> 4
        conv(4, 0,
             mkseg(hs1 + (long)s * 64 * HWp, 64, HWp, (long)Tn * 64 * HWp, 0),
             mkseg(hs0 + (long)pl * HWp, 1, 0, (long)Tn * HWp, 0), none,
             w_dec1, 65, b_dec1, nullptr, 0, 0, -1,
             z, 0, 4L * HWp, 65, 4, 1);
        long n1 = (long)Bn * HWp;
        lstm_k<<<(n1 + thr - 1) / thr, thr>>>(z, cs0 + (long)pl * HWp, (long)Tn * HWp,
                                              hs0 + (long)s * HWp, (long)Tn * HWp,
                                              cs0 + (long)s * HWp, (long)Tn * HWp,
                                              out + (long)s * HWp, 5L * HWp, 1);
    }
}

// round 3
// speedup vs baseline: 4.9715x; 1.3142x over previous
#include <cuda_runtime.h>
#include <math.h>

#define HWp 16384
#define Hdim 128
#define Wdim 128
#define Bn 8
#define Tn 10
#define Dn 10

// ---------------- scratch state (device globals) ----------------
__device__ float g_xx[(size_t)Bn*Tn*Dn*HWp];
__device__ float g_hs0[(size_t)Bn*Tn*HWp];
__device__ float g_cs0[(size_t)Bn*Tn*HWp];
__device__ float g_hs1[(size_t)Bn*Tn*64*HWp];
__device__ float g_cs1[(size_t)Bn*Tn*64*HWp];
__device__ float g_score[(size_t)Bn*Tn*HWp];
__device__ float g_hid[(size_t)Tn*Bn*32*HWp];
__device__ float g_z[(size_t)Bn*256*HWp];
__device__ float g_hatt[(size_t)Bn*64*HWp];
__device__ float g_tc[(size_t)Tn*Bn*32*HWp];

__device__ __forceinline__ float sigm(float x) { return 1.f / (1.f + __expf(-x)); }

__device__ __forceinline__ unsigned f2tf(float x) {
    unsigned r; asm("cvt.rna.tf32.f32 %0, %1;" : "=r"(r) : "f"(x)); return r;
}
__device__ __forceinline__ void mma8(float* c, const unsigned* a, const unsigned* b) {
    asm volatile("mma.sync.aligned.m16n8k8.row.col.f32.tf32.tf32.f32 "
        "{%0,%1,%2,%3}, {%4,%5,%6,%7}, {%8,%9}, {%0,%1,%2,%3};"
        : "+f"(c[0]), "+f"(c[1]), "+f"(c[2]), "+f"(c[3])
        : "r"(a[0]), "r"(a[1]), "r"(a[2]), "r"(a[3]), "r"(b[0]), "r"(b[1]));
}

// =============== implicit-GEMM 3x3 conv on tensor cores (tf32 mma.sync) ===============
// Block: 256 thr (8 warps) computes MBLK output channels x 256 px (16x16 tile).
// K loop: Cin in chunks of 8; per chunk, 9 tap-GEMMs over the staged halo tile.
// SPLIT=3: hi/lo tf32 split (~fp32 accuracy); SPLIT=1: plain tf32.
template <int MBLK, int WN, int SPLIT>
__global__ void __launch_bounds__(256) mmaconv(
    const float* __restrict__ in0, int n0, long c0s, long b0s, long r0s,
    const float* __restrict__ in1, int n1, long c1s, long b1s, long r1s,
    const float* __restrict__ in2, int n2, long c2s, long b2s, long r2s,
    const float* __restrict__ wgt, int Cw, const float* __restrict__ bias, int act,
    float* __restrict__ out, long o_rs, long obs, int Cin, int Cout)
{
    constexpr int WM = 8 / WN;
    constexpr int MT = MBLK / (16 * WM);
    constexpr int NT = 32 / WN;
    constexpr int S = MBLK + 8;

    __shared__ float in_t[8 * 360];     // 8 ci planes, 18 rows x 19 (stride 360)
    __shared__ float w_t[72 * S];       // [tap*8+ci][co], co padded

    int b = blockIdx.z % Bn;
    int r = blockIdx.z / Bn;
    int cobase = blockIdx.y * MBLK;
    int ty0 = (blockIdx.x >> 3) * 16, tx0 = (blockIdx.x & 7) * 16;

    int tid = threadIdx.x;
    int wid = tid >> 5, lane = tid & 31;
    int g = lane >> 2, q = lane & 3;
    int cowb = (wid / WN) * (MT * 16);
    int pwb  = (wid % WN) * (NT * 8);

    int pixoff[NT];
#pragma unroll
    for (int nt = 0; nt < NT; nt++) {
        int px = pwb + nt * 8 + g;
        pixoff[nt] = (px >> 4) * 19 + (px & 15);
    }

    float acc[MT][NT][4];
#pragma unroll
    for (int mt = 0; mt < MT; mt++)
#pragma unroll
        for (int nt = 0; nt < NT; nt++)
#pragma unroll
            for (int i = 0; i < 4; i++) acc[mt][nt][i] = 0.f;

    int nCh = (Cin + 7) >> 3;
    for (int cb = 0; cb < nCh; cb++) {
        // ---- stage 8 input halo planes ----
        for (int i = tid; i < 8 * 324; i += 256) {
            int ci = i / 324; int rem = i - ci * 324;
            int rr = rem / 18, cc = rem - rr * 18;
            int cig = cb * 8 + ci;
            float v = 0.f;
            if (cig < Cin) {
                const float* src;
                if (cig < n0)           src = in0 + (long)b * b0s + (long)r * r0s + (long)cig * c0s;
                else if (cig < n0 + n1) src = in1 + (long)b * b1s + (long)r * r1s + (long)(cig - n0) * c1s;
                else                    src = in2 + (long)b * b2s + (long)r * r2s + (long)(cig - n0 - n1) * c2s;
                int gy = ty0 + rr - 1, gx = tx0 + cc - 1;
                if (gy >= 0 && gy < Hdim && gx >= 0 && gx < Wdim) v = src[gy * Wdim + gx];
            }
            in_t[ci * 360 + rr * 19 + cc] = v;
        }
        // ---- stage weights [tap][ci][co] (global reads coalesced over ci*9+tap) ----
        for (int i = tid; i < MBLK * 72; i += 256) {
            int co = i / 72; int rem = i - co * 72;
            int ci = rem / 9, tap = rem - ci * 9;
            int cig = cb * 8 + ci;
            float wv = 0.f;
            if (cig < Cin && cobase + co < Cout)
                wv = wgt[((long)(cobase + co) * Cw + cig) * 9 + tap];
            w_t[(tap * 8 + ci) * S + co] = wv;
        }
        __syncthreads();

#pragma unroll
        for (int tap = 0; tap < 9; tap++) {
            int toff = (tap / 3) * 19 + (tap % 3);
            unsigned ahi[MT][4], alo[MT][4];
#pragma unroll
            for (int mt = 0; mt < MT; mt++) {
                int base = (tap * 8 + q) * S + cowb + mt * 16 + g;
                float a0 = w_t[base],         a1 = w_t[base + 8];
                float a2 = w_t[base + 4 * S], a3 = w_t[base + 4 * S + 8];
                ahi[mt][0] = f2tf(a0); ahi[mt][1] = f2tf(a1);
                ahi[mt][2] = f2tf(a2); ahi[mt][3] = f2tf(a3);
                if (SPLIT == 3) {
                    alo[mt][0] = f2tf(a0 - __uint_as_float(ahi[mt][0]));
                    alo[mt][1] = f2tf(a1 - __uint_as_float(ahi[mt][1]));
                    alo[mt][2] = f2tf(a2 - __uint_as_float(ahi[mt][2]));
                    alo[mt][3] = f2tf(a3 - __uint_as_float(ahi[mt][3]));
                }
            }
#pragma unroll
            for (int nt = 0; nt < NT; nt++) {
                float b0 = in_t[q * 360 + pixoff[nt] + toff];
                float b1 = in_t[(q + 4) * 360 + pixoff[nt] + toff];
                unsigned bhi[2] = { f2tf(b0), f2tf(b1) };
                unsigned blo[2];
                if (SPLIT == 3) {
                    blo[0] = f2tf(b0 - __uint_as_float(bhi[0]));
                    blo[1] = f2tf(b1 - __uint_as_float(bhi[1]));
                }
#pragma unroll
                for (int mt = 0; mt < MT; mt++) {
                    if (SPLIT == 3) {
                        mma8(acc[mt][nt], alo[mt], bhi);
                        mma8(acc[mt][nt], ahi[mt], blo);
                    }
                    mma8(acc[mt][nt], ahi[mt], bhi);
                }
            }
        }
        __syncthreads();
    }

    // ---- epilogue ----
#pragma unroll
    for (int mt = 0; mt < MT; mt++) {
#pragma unroll
        for (int half = 0; half < 2; half++) {
            int co = cobase + cowb + mt * 16 + g + half * 8;
            if (co >= Cout) continue;
            float bs = bias ? bias[co] : 0.f;
            float* op = out + (long)r * o_rs + (long)b * obs + (long)co * HWp;
#pragma unroll
            for (int nt = 0; nt < NT; nt++) {
                int px = pwb + nt * 8 + 2 * q;
                int gp = (ty0 + (px >> 4)) * Wdim + tx0 + (px & 15);
                float v0 = acc[mt][nt][half * 2] + bs;
                float v1 = acc[mt][nt][half * 2 + 1] + bs;
                if (act) { v0 = tanhf(v0); v1 = tanhf(v1); }
                op[gp] = v0; op[gp + 1] = v1;
            }
        }
    }
}

// =============== FFMA fallback conv (small Cout paths) ===============
template <int CB, int ACT>
__global__ void __launch_bounds__(256) convk(
    const float* __restrict__ in0, int n0, long c0s, long b0s, long r0s,
    const float* __restrict__ in1, int n1, long c1s, long b1s, long r1s,
    const float* __restrict__ in2, int n2, long c2s, long b2s, long r2s,
    const float* __restrict__ wgt, int Cw,
    const float* __restrict__ bias,
    const float* __restrict__ radd, long radd_rs, long radd_bs, int ring_s,
    float* __restrict__ out, long o_rs, long obs,
    int Cin, int Cout, int nCo)
{
    __shared__ float tile[2][34 * 34];
    __shared__ float wsm[2][CB][9];

    int z = blockIdx.z;
    int cb = z % nCo;
    int zb = z / nCo;
    int b = zb % Bn;
    int r = zb / Bn;
    int cobase = cb * CB;

    int tid = threadIdx.x;
    int txc = tid & 15, tyr = tid >> 4;
    int x0 = blockIdx.x * 32, y0 = blockIdx.y * 32;

    int goff[5]; bool gok[5];
#pragma unroll
    for (int j = 0; j < 5; j++) {
        int i = tid + j * 256;
        int rr = i / 34, cc = i - rr * 34;
        int gy = y0 + rr - 1, gx = x0 + cc - 1;
        gok[j] = (i < 34 * 34) && (gy >= 0) && (gy < Hdim) && (gx >= 0) && (gx < Wdim);
        goff[j] = gy * Wdim + gx;
    }
    bool wldr = tid < CB * 9;
    int wco = tid / 9, wk = tid - wco * 9;
    bool wok = wldr && (cobase + wco < Cout);
    long wbase = ((long)(cobase + wco) * Cw) * 9 + wk;

    float acc[CB][4];
#pragma unroll
    for (int co = 0; co < CB; co++)
#pragma unroll
        for (int qq = 0; qq < 4; qq++) acc[co][qq] = 0.f;

    auto load_cin = [&](int cin, int p) {
        const float* src;
        if (cin < n0)           src = in0 + (long)b * b0s + (long)r * r0s + (long)cin * c0s;
        else if (cin < n0 + n1) src = in1 + (long)b * b1s + (long)r * r1s + (long)(cin - n0) * c1s;
        else                    src = in2 + (long)b * b2s + (long)r * r2s + (long)(cin - n0 - n1) * c2s;
#pragma unroll
        for (int j = 0; j < 4; j++)
            tile[p][tid + j * 256] = gok[j] ? src[goff[j]] : 0.f;
        if (tid + 1024 < 34 * 34)
            tile[p][tid + 1024] = gok[4] ? src[goff[4]] : 0.f;
        if (wldr)
            wsm[p][wco][wk] = wok ? wgt[wbase + (long)cin * 9] : 0.f;
    };

    load_cin(0, 0);
    __syncthreads();

    for (int cin = 0; cin < Cin; cin++) {
        int p = cin & 1;
        if (cin + 1 < Cin) load_cin(cin + 1, p ^ 1);

        float v[4][4];
#pragma unroll
        for (int rr = 0; rr < 4; rr++)
#pragma unroll
            for (int cc = 0; cc < 4; cc++)
                v[rr][cc] = tile[p][(2 * tyr + rr) * 34 + 2 * txc + cc];

#pragma unroll
        for (int co = 0; co < CB; co++) {
#pragma unroll
            for (int k = 0; k < 9; k++) {
                float w = wsm[p][co][k];
                int dy = k / 3, dx = k % 3;
                acc[co][0] = fmaf(v[dy][dx],         w, acc[co][0]);
                acc[co][1] = fmaf(v[dy][dx + 1],     w, acc[co][1]);
                acc[co][2] = fmaf(v[dy + 1][dx],     w, acc[co][2]);
                acc[co][3] = fmaf(v[dy + 1][dx + 1], w, acc[co][3]);
            }
        }
        __syncthreads();
    }

    int ox = x0 + 2 * txc, oy = y0 + 2 * tyr;
    long p0 = (long)oy * Wdim + ox;
    int pr = (radd && ring_s >= 0) ? (ring_s + r) % Tn : r;
#pragma unroll
    for (int co = 0; co < CB; co++) {
        int c = cobase + co;
        if (c >= Cout) continue;
        float bs = bias ? bias[c] : 0.f;
        float v0 = acc[co][0] + bs, v1 = acc[co][1] + bs;
        float v2 = acc[co][2] + bs, v3 = acc[co][3] + bs;
        if (radd) {
            const float* ra = radd + (long)pr * radd_rs + (long)b * radd_bs + (long)c * HWp + p0;
            v0 += ra[0]; v1 += ra[1]; v2 += ra[Wdim]; v3 += ra[Wdim + 1];
        }
        if (ACT == 1) { v0 = tanhf(v0); v1 = tanhf(v1); v2 = tanhf(v2); v3 = tanhf(v3); }
        float* o = out + (long)r * o_rs + (long)b * obs + (long)c * HWp + p0;
        o[0] = v0; o[1] = v1; o[Wdim] = v2; o[Wdim + 1] = v3;
    }
}

// ---------------- LSTM pointwise gate update ----------------
__global__ void lstm_k(const float* __restrict__ z, const float* __restrict__ cin, long cin_bs,
                       float* __restrict__ hout, long h_bs, float* __restrict__ cout_, long c_bs,
                       float* __restrict__ hout2, long h2_bs, int C)
{
    long total = (long)Bn * C * HWp;
    long idx = (long)blockIdx.x * blockDim.x + threadIdx.x;
    if (idx >= total) return;
    long CHW = (long)C * HWp;
    int b = (int)(idx / CHW);
    long r = idx - (long)b * CHW;
    const float* zb = z + (long)b * 4 * CHW;
    float zi = zb[r], zf = zb[CHW + r], zo = zb[2 * CHW + r], zg = zb[3 * CHW + r];
    float c = cin[(long)b * cin_bs + r];
    float c2 = sigm(zf) * c + sigm(zi) * tanhf(zg);
    float h2 = sigm(zo) * tanhf(c2);
    hout[(long)b * h_bs + r] = h2;
    cout_[(long)b * c_bs + r] = c2;
    if (hout2) hout2[(long)b * h2_bs + r] = h2;
}

// ---------------- input attention softmax + compounding reweight ----------------
__global__ void inattn_k(const float* __restrict__ score, float* __restrict__ xx)
{
    int idx = blockIdx.x * blockDim.x + threadIdx.x;
    if (idx >= Bn * HWp) return;
    int b = idx / HWp, p = idx - b * HWp;
    const float* sc = score + (long)b * Dn * HWp + p;
    float s[Dn];
    float m = -1e30f;
#pragma unroll
    for (int k = 0; k < Dn; k++) { s[k] = sc[(long)k * HWp]; m = fmaxf(m, s[k]); }
    float sum = 0.f;
#pragma unroll
    for (int k = 0; k < Dn; k++) { s[k] = __expf(s[k] - m); sum += s[k]; }
    float inv = 1.f / sum;
    float* xb = xx + (long)b * Tn * Dn * HWp + p;
#pragma unroll
    for (int k = 0; k < Dn; k++) {
        float a = s[k] * inv;
        for (int t = 0; t < Tn; t++) xb[((long)t * Dn + k) * HWp] *= a;
    }
}

// ---------------- temporal attention softmax + weighted sum ----------------
__global__ void tattn_k(const float* __restrict__ score, const float* __restrict__ hs1,
                        float* __restrict__ hatt, int s)
{
    int idx = blockIdx.x * blockDim.x + threadIdx.x;
    if (idx >= Bn * HWp) return;
    int b = idx / HWp, p = idx - b * HWp;
    const float* sc = score + (long)b * Tn * HWp + p;
    float bt[Tn];
    float m = -1e30f;
#pragma unroll
    for (int t = 0; t < Tn; t++) { bt[t] = sc[(long)t * HWp]; m = fmaxf(m, bt[t]); }
    float sum = 0.f;
#pragma unroll
    for (int t = 0; t < Tn; t++) { bt[t] = __expf(bt[t] - m); sum += bt[t]; }
    float inv = 1.f / sum;
    float acc[64];
#pragma unroll
    for (int c = 0; c < 64; c++) acc[c] = 0.f;
    for (int t = 0; t < Tn; t++) {
        int phys = (s + t) % Tn;
        const float* hb = hs1 + ((long)b * Tn + phys) * 64 * HWp + p;
        float w = bt[t] * inv;
#pragma unroll
        for (int c = 0; c < 64; c++) acc[c] = fmaf(hb[(long)c * HWp], w, acc[c]);
    }
    float* ob = hatt + (long)b * 64 * HWp + p;
#pragma unroll
    for (int c = 0; c < 64; c++) ob[(long)c * HWp] = acc[c];
}

// ---------------- host side ----------------
struct Seg { const float* p; int n; long cs, bs, rs; };
static inline Seg mkseg(const float* p, int n, long cs, long bs, long rs) {
    Seg s; s.p = p; s.n = n; s.cs = cs; s.bs = bs; s.rs = rs; return s;
}

static void conv(int CB, int ACT, Seg a, Seg b, Seg c,
                 const float* w, int Cw, const float* bias,
                 const float* radd, long rrs, long rbs, int ring_s,
                 float* out, long ors, long obs, int Cin, int Cout, int R)
{
    int nCo = (Cout + CB - 1) / CB;
    dim3 grid(Wdim / 32, Hdim / 32, R * Bn * nCo);
#define CARGS a.p, a.n, a.cs, a.bs, a.rs, b.p, b.n, b.cs, b.bs, b.rs, c.p, c.n, c.cs, c.bs, c.rs, \
              w, Cw, bias, radd, rrs, rbs, ring_s, out, ors, obs, Cin, Cout, nCo
    if (CB == 8 && ACT == 1) convk<8, 1><<<grid, 256>>>(CARGS);
    else if (CB == 8)        convk<8, 0><<<grid, 256>>>(CARGS);
    else                     convk<1, 0><<<grid, 256>>>(CARGS);
#undef CARGS
}

static void mconv(int MBLK, int SPLIT, Seg a, Seg b, Seg c,
                  const float* w, int Cw, const float* bias, int act,
                  float* out, long ors, long obs, int Cin, int Cout, int R)
{
    dim3 grid(64, (Cout + MBLK - 1) / MBLK, R * Bn);
#define MARGS a.p, a.n, a.cs, a.bs, a.rs, b.p, b.n, b.cs, b.bs, b.rs, c.p, c.n, c.cs, c.bs, c.rs, \
              w, Cw, bias, act, out, ors, obs, Cin, Cout
    if (MBLK == 64)                     mmaconv<64, 4, 3><<<grid, 256>>>(MARGS);
    else if (MBLK == 32 && SPLIT == 1)  mmaconv<32, 8, 1><<<grid, 256>>>(MARGS);
    else if (MBLK == 32)                mmaconv<32, 8, 3><<<grid, 256>>>(MARGS);
    else                                mmaconv<16, 8, 3><<<grid, 256>>>(MARGS);
#undef MARGS
}

extern "C" void kernel_launch(void* const* d_in, const int* in_sizes, int n_in,
                              void* d_out, int out_size)
{
    const float* x      = (const float*)d_in[0];
    const float* h0     = (const float*)d_in[1];
    const float* c0     = (const float*)d_in[2];
    const float* h1     = (const float*)d_in[3];
    const float* c1     = (const float*)d_in[4];
    const float* w_enc0 = (const float*)d_in[5];
    const float* b_enc0 = (const float*)d_in[6];
    const float* w_enc1 = (const float*)d_in[7];
    const float* b_enc1 = (const float*)d_in[8];
    const float* w_dec0 = (const float*)d_in[9];
    const float* b_dec0 = (const float*)d_in[10];
    const float* w_dec1 = (const float*)d_in[11];
    const float* b_dec1 = (const float*)d_in[12];
    const float* wa1    = (const float*)d_in[13];
    const float* ba1    = (const float*)d_in[14];
    const float* wa2    = (const float*)d_in[15];
    const float* ba2    = (const float*)d_in[16];
    const float* wt1    = (const float*)d_in[17];
    const float* bt1    = (const float*)d_in[18];
    const float* wt2    = (const float*)d_in[19];
    const float* bt2    = (const float*)d_in[20];

    float *xx, *hs0, *cs0, *hs1, *cs1, *score, *hid, *z, *hatt, *tc;
    cudaGetSymbolAddress((void**)&xx, g_xx);
    cudaGetSymbolAddress((void**)&hs0, g_hs0);
    cudaGetSymbolAddress((void**)&cs0, g_cs0);
    cudaGetSymbolAddress((void**)&hs1, g_hs1);
    cudaGetSymbolAddress((void**)&cs1, g_cs1);
    cudaGetSymbolAddress((void**)&score, g_score);
    cudaGetSymbolAddress((void**)&hid, g_hid);
    cudaGetSymbolAddress((void**)&z, g_z);
    cudaGetSymbolAddress((void**)&hatt, g_hatt);
    cudaGetSymbolAddress((void**)&tc, g_tc);

    cudaMemcpyAsync(xx, x, sizeof(float) * (size_t)Bn * Tn * Dn * HWp,
                    cudaMemcpyDeviceToDevice);

    Seg none = mkseg(nullptr, 0, 0, 0, 0);
    const int thr = 256;
    const long HID_RS = (long)Bn * 32 * HWp;

    // ======== encoder layer 0 (hidden 1), compounding input attention ========
    for (int t = 0; t < Tn; t++) {
        const float* hp = (t == 0) ? h0 : hs0 + (long)(t - 1) * HWp;
        long hbs        = (t == 0) ? (long)HWp : (long)Tn * HWp;
        const float* cp = (t == 0) ? c0 : cs0 + (long)(t - 1) * HWp;
        long cbs = hbs;

        // attn conv1 (12->32, tanh) for all D features: tensor cores, 3xTF32
        mconv(32, 3,
              mkseg(xx, Tn, (long)Dn * HWp, (long)Tn * Dn * HWp, (long)HWp),
              mkseg(hp, 1, 0, hbs, 0),
              mkseg(cp, 1, 0, cbs, 0),
              wa1, 12, ba1, 1,
              hid, HID_RS, 32L * HWp, 12, 32, Dn);
        // attn conv2 (32->1) all features: FFMA
        conv(1, 0,
             mkseg(hid, 32, HWp, 32L * HWp, HID_RS), none, none,
             wa2, 32, ba2, nullptr, 0, 0, -1,
             score, (long)HWp, (long)Dn * HWp, 32, 1, Dn);
        inattn_k<<<(Bn * HWp + thr - 1) / thr, thr>>>(score, xx);

        // enc0 gate conv (11->4): tensor cores
        mconv(16, 3,
              mkseg(xx + (long)t * Dn * HWp, Dn, (long)HWp, (long)Tn * Dn * HWp, 0),
              mkseg(hp, 1, 0, hbs, 0), none,
              w_enc0, 11, b_enc0, 0,
              z, 0, 4L * HWp, 11, 4, 1);
        long n = (long)Bn * HWp;
        lstm_k<<<(n + thr - 1) / thr, thr>>>(z, cp, cbs,
                                             hs0 + (long)t * HWp, (long)Tn * HWp,
                                             cs0 + (long)t * HWp, (long)Tn * HWp,
                                             nullptr, 0, 1);
    }

    // ======== encoder layer 1 (65->256): tensor cores, 3xTF32 ========
    for (int t = 0; t < Tn; t++) {
        const float* hp = (t == 0) ? h1 : hs1 + (long)(t - 1) * 64 * HWp;
        long hbs        = (t == 0) ? 64L * HWp : (long)Tn * 64 * HWp;
        const float* cp = (t == 0) ? c1 : cs1 + (long)(t - 1) * 64 * HWp;

        mconv(64, 3,
              mkseg(hs0 + (long)t * HWp, 1, 0, (long)Tn * HWp, 0),
              mkseg(hp, 64, HWp, hbs, 0), none,
              w_enc1, 65, b_enc1, 0,
              z, 0, 256L * HWp, 65, 256, 1);
        long n = (long)Bn * 64 * HWp;
        lstm_k<<<(n + thr - 1) / thr, thr>>>(z, cp, hbs,
                                             hs1 + (long)t * 64 * HWp, (long)Tn * 64 * HWp,
                                             cs1 + (long)t * 64 * HWp, (long)Tn * 64 * HWp,
                                             nullptr, 0, 64);
    }

    // ======== temporal-attn h/c conv cache (128->32) all slots: tensor, 1xTF32 ========
    mconv(32, 1,
          mkseg(hs1, 64, HWp, (long)Tn * 64 * HWp, 64L * HWp),
          mkseg(cs1, 64, HWp, (long)Tn * 64 * HWp, 64L * HWp), none,
          wt1 + 9, 129, bt1, 0,
          tc, HID_RS, 32L * HWp, 128, 32, Tn);

    // ======== decoder ========
    float* out = (float*)d_out;
    for (int s = 0; s < 5; s++) {
        const float* yp; long ybs;
        if (s == 0) { yp = x + 90L * HWp; ybs = 100L * HWp; }
        else        { yp = hs0 + (long)(s - 1) * HWp; ybs = (long)Tn * HWp; }

        // hid[t] = tanh(conv_y(y) + tc[(s+t)%10]) : FFMA (tiny Cin=1)
        conv(8, 1,
             mkseg(yp, 1, 0, ybs, 0), none, none,
             wt1, 129, nullptr, tc, HID_RS, 32L * HWp, s,
             hid, HID_RS, 32L * HWp, 1, 32, Tn);
        conv(1, 0,
             mkseg(hid, 32, HWp, 32L * HWp, HID_RS), none, none,
             wt2, 32, bt2, nullptr, 0, 0, -1,
             score, (long)HWp, (long)Tn * HWp, 32, 1, Tn);
        tattn_k<<<(Bn * HWp + thr - 1) / thr, thr>>>(score, hs1, hatt, s);

        int pl = (s + 9) % Tn;

        // decoder L0 (65->256): tensor cores, 3xTF32
        mconv(64, 3,
              mkseg(yp, 1, 0, ybs, 0),
              mkseg(hatt, 64, HWp, 64L * HWp, 0), none,
              w_dec0, 65, b_dec0, 0,
              z, 0, 256L * HWp, 65, 256, 1);
        long n64 = (long)Bn * 64 * HWp;
        lstm_k<<<(n64 + thr - 1) / thr, thr>>>(z, cs1 + (long)pl * 64 * HWp, (long)Tn * 64 * HWp,
                                               hs1 + (long)s * 64 * HWp, (long)Tn * 64 * HWp,
                                               cs1 + (long)s * 64 * HWp, (long)Tn * 64 * HWp,
                                               nullptr, 0, 64);

        // refresh tc cache for slot s: tensor, 1xTF32
        mconv(32, 1,
              mkseg(hs1 + (long)s * 64 * HWp, 64, HWp, (long)Tn * 64 * HWp, 0),
              mkseg(cs1 + (long)s * 64 * HWp, 64, HWp, (long)Tn * 64 * HWp, 0), none,
              wt1 + 9, 129, bt1, 0,
              tc + (long)s * HID_RS, 0, 32L * HWp, 128, 32, 1);

        // decoder L1 (65->4): tensor cores
        mconv(16, 3,
              mkseg(hs1 + (long)s * 64 * HWp, 64, HWp, (long)Tn * 64 * HWp, 0),
              mkseg(hs0 + (long)pl * HWp, 1, 0, (long)Tn * HWp, 0), none,
              w_dec1, 65, b_dec1, 0,
              z, 0, 4L * HWp, 65, 4, 1);
        long n1 = (long)Bn * HWp;
        lstm_k<<<(n1 + thr - 1) / thr, thr>>>(z, cs0 + (long)pl * HWp, (long)Tn * HWp,
                                              hs0 + (long)s * HWp, (long)Tn * HWp,
                                              cs0 + (long)s * HWp, (long)Tn * HWp,
                                              out + (long)s * HWp, 5L * HWp, 1);
    }
}

// round 4
// speedup vs baseline: 5.8280x; 1.1723x over previous
#include <cuda_runtime.h>
#include <math.h>

#define HWp 16384
#define Hdim 128
#define Wdim 128
#define Bn 8
#define Tn 10
#define Dn 10

// ---------------- scratch state (device globals) ----------------
__device__ float g_xx[(size_t)Bn*Tn*Dn*HWp];
__device__ float g_hs0[(size_t)Bn*Tn*HWp];
__device__ float g_cs0[(size_t)Bn*Tn*HWp];
__device__ float g_hs1[(size_t)Bn*Tn*64*HWp];
__device__ float g_cs1[(size_t)Bn*Tn*64*HWp];
__device__ float g_score[(size_t)Bn*Tn*HWp];
__device__ float g_hid[(size_t)Tn*Bn*32*HWp];
__device__ float g_z[(size_t)Bn*256*HWp];
__device__ float g_hatt[(size_t)Bn*64*HWp];
__device__ float g_tc[(size_t)Tn*Bn*32*HWp];

__device__ __forceinline__ float sigm(float x) { return 1.f / (1.f + __expf(-x)); }

__device__ __forceinline__ unsigned f2tf(float x) {
    unsigned r; asm("cvt.rna.tf32.f32 %0, %1;" : "=r"(r) : "f"(x)); return r;
}
__device__ __forceinline__ void mma8(float* c, const unsigned* a, const unsigned* b) {
    asm volatile("mma.sync.aligned.m16n8k8.row.col.f32.tf32.tf32.f32 "
        "{%0,%1,%2,%3}, {%4,%5,%6,%7}, {%8,%9}, {%0,%1,%2,%3};"
        : "+f"(c[0]), "+f"(c[1]), "+f"(c[2]), "+f"(c[3])
        : "r"(a[0]), "r"(a[1]), "r"(a[2]), "r"(a[3]), "r"(b[0]), "r"(b[1]));
}

// =============== implicit-GEMM 3x3 conv on tensor cores (tf32 mma.sync) ===============
// Block: 256 thr (8 warps), MBLK output channels x 256 px (16x16 tile).
// Cin chunks of 8; per chunk 9 tap-GEMMs. Inputs & weights pre-converted to
// tf32 hi/lo in smem at stage time; weights stored in mma-fragment order so
// each A fragment is one LDS.128. Inner loop = LDS + MMA only.
template <int MBLK, int WN, int SPLIT>
__global__ void __launch_bounds__(256) mmaconv(
    const float* __restrict__ in0, int n0, long c0s, long b0s, long r0s,
    const float* __restrict__ in1, int n1, long c1s, long b1s, long r1s,
    const float* __restrict__ in2, int n2, long c2s, long b2s, long r2s,
    const float* __restrict__ wgt, int Cw, const float* __restrict__ bias, int act,
    float* __restrict__ out, long o_rs, long obs, int Cin, int Cout)
{
    constexpr int WM = 8 / WN;
    constexpr int MT = MBLK / (16 * WM);
    constexpr int NT = 32 / WN;
    constexpr int MTtot = MBLK / 16;
    constexpr int WSZ = 9 * MTtot * 128;   // fragment-order weights per chunk

    __shared__ unsigned in_hi[8 * 360];
    __shared__ unsigned in_lo[(SPLIT == 3) ? 8 * 360 : 1];
    __shared__ unsigned w_hi[WSZ];
    __shared__ unsigned w_lo[(SPLIT == 3) ? WSZ : 1];

    int b = blockIdx.z % Bn;
    int r = blockIdx.z / Bn;
    int cobase = blockIdx.y * MBLK;
    int ty0 = (blockIdx.x >> 3) * 16, tx0 = (blockIdx.x & 7) * 16;

    int tid = threadIdx.x;
    int wid = tid >> 5, lane = tid & 31;
    int g = lane >> 2, q = lane & 3;
    int cowb = (wid / WN) * (MT * 16);
    int pwb  = (wid % WN) * (NT * 8);

    int pixoff[NT];
#pragma unroll
    for (int nt = 0; nt < NT; nt++) {
        int px = pwb + nt * 8 + g;
        pixoff[nt] = (px >> 4) * 19 + (px & 15);
    }

    float acc[MT][NT][4];
#pragma unroll
    for (int mt = 0; mt < MT; mt++)
#pragma unroll
        for (int nt = 0; nt < NT; nt++)
#pragma unroll
            for (int i = 0; i < 4; i++) acc[mt][nt][i] = 0.f;

    int nCh = (Cin + 7) >> 3;
    for (int cb = 0; cb < nCh; cb++) {
        // ---- stage 8 input halo planes, pre-converted hi/lo ----
        for (int i = tid; i < 8 * 324; i += 256) {
            int ci = i / 324; int rem = i - ci * 324;
            int rr = rem / 18, cc = rem - rr * 18;
            int cig = cb * 8 + ci;
            float v = 0.f;
            if (cig < Cin) {
                const float* src;
                if (cig < n0)           src = in0 + (long)b * b0s + (long)r * r0s + (long)cig * c0s;
                else if (cig < n0 + n1) src = in1 + (long)b * b1s + (long)r * r1s + (long)(cig - n0) * c1s;
                else                    src = in2 + (long)b * b2s + (long)r * r2s + (long)(cig - n0 - n1) * c2s;
                int gy = ty0 + rr - 1, gx = tx0 + cc - 1;
                if (gy >= 0 && gy < Hdim && gx >= 0 && gx < Wdim) v = src[gy * Wdim + gx];
            }
            unsigned hi = f2tf(v);
            in_hi[ci * 360 + rr * 19 + cc] = hi;
            if (SPLIT == 3)
                in_lo[ci * 360 + rr * 19 + cc] = f2tf(v - __uint_as_float(hi));
        }
        // ---- stage weights in mma-fragment order, pre-converted hi/lo ----
        // layout: w[(tap*MTtot + mtile)*128 + lane*4 + j]
        // j=0:(row g,k q) j=1:(row g+8,k q) j=2:(row g,k q+4) j=3:(row g+8,k q+4)
        for (int e = tid; e < WSZ; e += 256) {
            int tap = e / (MTtot * 128);
            int rem = e - tap * (MTtot * 128);
            int mtile = rem >> 7;
            int li = rem & 127;
            int ln = li >> 2, j = li & 3;
            int lg = ln >> 2, lq = ln & 3;
            int co = cobase + mtile * 16 + lg + (j & 1) * 8;
            int k = lq + (j >> 1) * 4;
            int cig = cb * 8 + k;
            float wv = 0.f;
            if (cig < Cin && co < Cout)
                wv = wgt[((long)co * Cw + cig) * 9 + tap];
            unsigned hi = f2tf(wv);
            w_hi[e] = hi;
            if (SPLIT == 3)
                w_lo[e] = f2tf(wv - __uint_as_float(hi));
        }
        __syncthreads();

#pragma unroll
        for (int tap = 0; tap < 9; tap++) {
            int toff = (tap / 3) * 19 + (tap % 3);
            uint4 ahi[MT], alo[MT];
#pragma unroll
            for (int mt = 0; mt < MT; mt++) {
                int mtile = (cowb >> 4) + mt;
                int fb = (tap * MTtot + mtile) * 128 + lane * 4;
                ahi[mt] = *(const uint4*)&w_hi[fb];
                if (SPLIT == 3) alo[mt] = *(const uint4*)&w_lo[fb];
            }
            const unsigned* bh0 = &in_hi[q * 360 + toff];
            const unsigned* bh1 = &in_hi[(q + 4) * 360 + toff];
            const unsigned* bl0 = &in_lo[(SPLIT == 3) ? q * 360 + toff : 0];
            const unsigned* bl1 = &in_lo[(SPLIT == 3) ? (q + 4) * 360 + toff : 0];
#pragma unroll
            for (int nt = 0; nt < NT; nt++) {
                unsigned bhi[2] = { bh0[pixoff[nt]], bh1[pixoff[nt]] };
                unsigned blo[2];
                if (SPLIT == 3) { blo[0] = bl0[pixoff[nt]]; blo[1] = bl1[pixoff[nt]]; }
#pragma unroll
                for (int mt = 0; mt < MT; mt++) {
                    if (SPLIT == 3) {
                        mma8(acc[mt][nt], (const unsigned*)&alo[mt], bhi);
                        mma8(acc[mt][nt], (const unsigned*)&ahi[mt], blo);
                    }
                    mma8(acc[mt][nt], (const unsigned*)&ahi[mt], bhi);
                }
            }
        }
        __syncthreads();
    }

    // ---- epilogue ----
#pragma unroll
    for (int mt = 0; mt < MT; mt++) {
#pragma unroll
        for (int half = 0; half < 2; half++) {
            int co = cobase + cowb + mt * 16 + g + half * 8;
            if (co >= Cout) continue;
            float bs = bias ? bias[co] : 0.f;
            float* op = out + (long)r * o_rs + (long)b * obs + (long)co * HWp;
#pragma unroll
            for (int nt = 0; nt < NT; nt++) {
                int px = pwb + nt * 8 + 2 * q;
                int gp = (ty0 + (px >> 4)) * Wdim + tx0 + (px & 15);
                float v0 = acc[mt][nt][half * 2] + bs;
                float v1 = acc[mt][nt][half * 2 + 1] + bs;
                if (act) { v0 = tanhf(v0); v1 = tanhf(v1); }
                op[gp] = v0; op[gp + 1] = v1;
            }
        }
    }
}

// =============== FFMA fallback conv (small Cout paths) ===============
template <int CB, int ACT>
__global__ void __launch_bounds__(256) convk(
    const float* __restrict__ in0, int n0, long c0s, long b0s, long r0s,
    const float* __restrict__ in1, int n1, long c1s, long b1s, long r1s,
    const float* __restrict__ in2, int n2, long c2s, long b2s, long r2s,
    const float* __restrict__ wgt, int Cw,
    const float* __restrict__ bias,
    const float* __restrict__ radd, long radd_rs, long radd_bs, int ring_s,
    float* __restrict__ out, long o_rs, long obs,
    int Cin, int Cout, int nCo)
{
    __shared__ float tile[2][34 * 34];
    __shared__ float wsm[2][CB][9];

    int z = blockIdx.z;
    int cb = z % nCo;
    int zb = z / nCo;
    int b = zb % Bn;
    int r = zb / Bn;
    int cobase = cb * CB;

    int tid = threadIdx.x;
    int txc = tid & 15, tyr = tid >> 4;
    int x0 = blockIdx.x * 32, y0 = blockIdx.y * 32;

    int goff[5]; bool gok[5];
#pragma unroll
    for (int j = 0; j < 5; j++) {
        int i = tid + j * 256;
        int rr = i / 34, cc = i - rr * 34;
        int gy = y0 + rr - 1, gx = x0 + cc - 1;
        gok[j] = (i < 34 * 34) && (gy >= 0) && (gy < Hdim) && (gx >= 0) && (gx < Wdim);
        goff[j] = gy * Wdim + gx;
    }
    bool wldr = tid < CB * 9;
    int wco = tid / 9, wk = tid - wco * 9;
    bool wok = wldr && (cobase + wco < Cout);
    long wbase = ((long)(cobase + wco) * Cw) * 9 + wk;

    float acc[CB][4];
#pragma unroll
    for (int co = 0; co < CB; co++)
#pragma unroll
        for (int qq = 0; qq < 4; qq++) acc[co][qq] = 0.f;

    auto load_cin = [&](int cin, int p) {
        const float* src;
        if (cin < n0)           src = in0 + (long)b * b0s + (long)r * r0s + (long)cin * c0s;
        else if (cin < n0 + n1) src = in1 + (long)b * b1s + (long)r * r1s + (long)(cin - n0) * c1s;
        else                    src = in2 + (long)b * b2s + (long)r * r2s + (long)(cin - n0 - n1) * c2s;
#pragma unroll
        for (int j = 0; j < 4; j++)
            tile[p][tid + j * 256] = gok[j] ? src[goff[j]] : 0.f;
        if (tid + 1024 < 34 * 34)
            tile[p][tid + 1024] = gok[4] ? src[goff[4]] : 0.f;
        if (wldr)
            wsm[p][wco][wk] = wok ? wgt[wbase + (long)cin * 9] : 0.f;
    };

    load_cin(0, 0);
    __syncthreads();

    for (int cin = 0; cin < Cin; cin++) {
        int p = cin & 1;
        if (cin + 1 < Cin) load_cin(cin + 1, p ^ 1);

        float v[4][4];
#pragma unroll
        for (int rr = 0; rr < 4; rr++)
#pragma unroll
            for (int cc = 0; cc < 4; cc++)
                v[rr][cc] = tile[p][(2 * tyr + rr) * 34 + 2 * txc + cc];

#pragma unroll
        for (int co = 0; co < CB; co++) {
#pragma unroll
            for (int k = 0; k < 9; k++) {
                float w = wsm[p][co][k];
                int dy = k / 3, dx = k % 3;
                acc[co][0] = fmaf(v[dy][dx],         w, acc[co][0]);
                acc[co][1] = fmaf(v[dy][dx + 1],     w, acc[co][1]);
                acc[co][2] = fmaf(v[dy + 1][dx],     w, acc[co][2]);
                acc[co][3] = fmaf(v[dy + 1][dx + 1], w, acc[co][3]);
            }
        }
        __syncthreads();
    }

    int ox = x0 + 2 * txc, oy = y0 + 2 * tyr;
    long p0 = (long)oy * Wdim + ox;
    int pr = (radd && ring_s >= 0) ? (ring_s + r) % Tn : r;
#pragma unroll
    for (int co = 0; co < CB; co++) {
        int c = cobase + co;
        if (c >= Cout) continue;
        float bs = bias ? bias[c] : 0.f;
        float v0 = acc[co][0] + bs, v1 = acc[co][1] + bs;
        float v2 = acc[co][2] + bs, v3 = acc[co][3] + bs;
        if (radd) {
            const float* ra = radd + (long)pr * radd_rs + (long)b * radd_bs + (long)c * HWp + p0;
            v0 += ra[0]; v1 += ra[1]; v2 += ra[Wdim]; v3 += ra[Wdim + 1];
        }
        if (ACT == 1) { v0 = tanhf(v0); v1 = tanhf(v1); v2 = tanhf(v2); v3 = tanhf(v3); }
        float* o = out + (long)r * o_rs + (long)b * obs + (long)c * HWp + p0;
        o[0] = v0; o[1] = v1; o[Wdim] = v2; o[Wdim + 1] = v3;
    }
}

// ---------------- LSTM pointwise gate update ----------------
__global__ void lstm_k(const float* __restrict__ z, const float* __restrict__ cin, long cin_bs,
                       float* __restrict__ hout, long h_bs, float* __restrict__ cout_, long c_bs,
                       float* __restrict__ hout2, long h2_bs, int C)
{
    long total = (long)Bn * C * HWp;
    long idx = (long)blockIdx.x * blockDim.x + threadIdx.x;
    if (idx >= total) return;
    long CHW = (long)C * HWp;
    int b = (int)(idx / CHW);
    long r = idx - (long)b * CHW;
    const float* zb = z + (long)b * 4 * CHW;
    float zi = zb[r], zf = zb[CHW + r], zo = zb[2 * CHW + r], zg = zb[3 * CHW + r];
    float c = cin[(long)b * cin_bs + r];
    float c2 = sigm(zf) * c + sigm(zi) * tanhf(zg);
    float h2 = sigm(zo) * tanhf(c2);
    hout[(long)b * h_bs + r] = h2;
    cout_[(long)b * c_bs + r] = c2;
    if (hout2) hout2[(long)b * h2_bs + r] = h2;
}

// ---------------- input attention softmax + compounding reweight ----------------
__global__ void inattn_k(const float* __restrict__ score, float* __restrict__ xx)
{
    int idx = blockIdx.x * blockDim.x + threadIdx.x;
    if (idx >= Bn * HWp) return;
    int b = idx / HWp, p = idx - b * HWp;
    const float* sc = score + (long)b * Dn * HWp + p;
    float s[Dn];
    float m = -1e30f;
#pragma unroll
    for (int k = 0; k < Dn; k++) { s[k] = sc[(long)k * HWp]; m = fmaxf(m, s[k]); }
    float sum = 0.f;
#pragma unroll
    for (int k = 0; k < Dn; k++) { s[k] = __expf(s[k] - m); sum += s[k]; }
    float inv = 1.f / sum;
    float* xb = xx + (long)b * Tn * Dn * HWp + p;
#pragma unroll
    for (int k = 0; k < Dn; k++) {
        float a = s[k] * inv;
        for (int t = 0; t < Tn; t++) xb[((long)t * Dn + k) * HWp] *= a;
    }
}

// ---------------- temporal attention softmax + weighted sum ----------------
__global__ void tattn_k(const float* __restrict__ score, const float* __restrict__ hs1,
                        float* __restrict__ hatt, int s)
{
    int idx = blockIdx.x * blockDim.x + threadIdx.x;
    if (idx >= Bn * HWp) return;
    int b = idx / HWp, p = idx - b * HWp;
    const float* sc = score + (long)b * Tn * HWp + p;
    float bt[Tn];
    float m = -1e30f;
#pragma unroll
    for (int t = 0; t < Tn; t++) { bt[t] = sc[(long)t * HWp]; m = fmaxf(m, bt[t]); }
    float sum = 0.f;
#pragma unroll
    for (int t = 0; t < Tn; t++) { bt[t] = __expf(bt[t] - m); sum += bt[t]; }
    float inv = 1.f / sum;
    float acc[64];
#pragma unroll
    for (int c = 0; c < 64; c++) acc[c] = 0.f;
    for (int t = 0; t < Tn; t++) {
        int phys = (s + t) % Tn;
        const float* hb = hs1 + ((long)b * Tn + phys) * 64 * HWp + p;
        float w = bt[t] * inv;
#pragma unroll
        for (int c = 0; c < 64; c++) acc[c] = fmaf(hb[(long)c * HWp], w, acc[c]);
    }
    float* ob = hatt + (long)b * 64 * HWp + p;
#pragma unroll
    for (int c = 0; c < 64; c++) ob[(long)c * HWp] = acc[c];
}

// ---------------- host side ----------------
struct Seg { const float* p; int n; long cs, bs, rs; };
static inline Seg mkseg(const float* p, int n, long cs, long bs, long rs) {
    Seg s; s.p = p; s.n = n; s.cs = cs; s.bs = bs; s.rs = rs; return s;
}

static void conv(int CB, int ACT, Seg a, Seg b, Seg c,
                 const float* w, int Cw, const float* bias,
                 const float* radd, long rrs, long rbs, int ring_s,
                 float* out, long ors, long obs, int Cin, int Cout, int R)
{
    int nCo = (Cout + CB - 1) / CB;
    dim3 grid(Wdim / 32, Hdim / 32, R * Bn * nCo);
#define CARGS a.p, a.n, a.cs, a.bs, a.rs, b.p, b.n, b.cs, b.bs, b.rs, c.p, c.n, c.cs, c.bs, c.rs, \
              w, Cw, bias, radd, rrs, rbs, ring_s, out, ors, obs, Cin, Cout, nCo
    if (CB == 8 && ACT == 1) convk<8, 1><<<grid, 256>>>(CARGS);
    else if (CB == 8)        convk<8, 0><<<grid, 256>>>(CARGS);
    else                     convk<1, 0><<<grid, 256>>>(CARGS);
#undef CARGS
}

static void mconv(int MBLK, int SPLIT, Seg a, Seg b, Seg c,
                  const float* w, int Cw, const float* bias, int act,
                  float* out, long ors, long obs, int Cin, int Cout, int R)
{
    dim3 grid(64, (Cout + MBLK - 1) / MBLK, R * Bn);
#define MARGS a.p, a.n, a.cs, a.bs, a.rs, b.p, b.n, b.cs, b.bs, b.rs, c.p, c.n, c.cs, c.bs, c.rs, \
              w, Cw, bias, act, out, ors, obs, Cin, Cout
    if (MBLK == 64)                     mmaconv<64, 4, 3><<<grid, 256>>>(MARGS);
    else if (MBLK == 32 && SPLIT == 1)  mmaconv<32, 8, 1><<<grid, 256>>>(MARGS);
    else if (MBLK == 32)                mmaconv<32, 8, 3><<<grid, 256>>>(MARGS);
    else                                mmaconv<16, 8, 3><<<grid, 256>>>(MARGS);
#undef MARGS
}

extern "C" void kernel_launch(void* const* d_in, const int* in_sizes, int n_in,
                              void* d_out, int out_size)
{
    const float* x      = (const float*)d_in[0];
    const float* h0     = (const float*)d_in[1];
    const float* c0     = (const float*)d_in[2];
    const float* h1     = (const float*)d_in[3];
    const float* c1     = (const float*)d_in[4];
    const float* w_enc0 = (const float*)d_in[5];
    const float* b_enc0 = (const float*)d_in[6];
    const float* w_enc1 = (const float*)d_in[7];
    const float* b_enc1 = (const float*)d_in[8];
    const float* w_dec0 = (const float*)d_in[9];
    const float* b_dec0 = (const float*)d_in[10];
    const float* w_dec1 = (const float*)d_in[11];
    const float* b_dec1 = (const float*)d_in[12];
    const float* wa1    = (const float*)d_in[13];
    const float* ba1    = (const float*)d_in[14];
    const float* wa2    = (const float*)d_in[15];
    const float* ba2    = (const float*)d_in[16];
    const float* wt1    = (const float*)d_in[17];
    const float* bt1    = (const float*)d_in[18];
    const float* wt2    = (const float*)d_in[19];
    const float* bt2    = (const float*)d_in[20];

    float *xx, *hs0, *cs0, *hs1, *cs1, *score, *hid, *z, *hatt, *tc;
    cudaGetSymbolAddress((void**)&xx, g_xx);
    cudaGetSymbolAddress((void**)&hs0, g_hs0);
    cudaGetSymbolAddress((void**)&cs0, g_cs0);
    cudaGetSymbolAddress((void**)&hs1, g_hs1);
    cudaGetSymbolAddress((void**)&cs1, g_cs1);
    cudaGetSymbolAddress((void**)&score, g_score);
    cudaGetSymbolAddress((void**)&hid, g_hid);
    cudaGetSymbolAddress((void**)&z, g_z);
    cudaGetSymbolAddress((void**)&hatt, g_hatt);
    cudaGetSymbolAddress((void**)&tc, g_tc);

    cudaMemcpyAsync(xx, x, sizeof(float) * (size_t)Bn * Tn * Dn * HWp,
                    cudaMemcpyDeviceToDevice);

    Seg none = mkseg(nullptr, 0, 0, 0, 0);
    const int thr = 256;
    const long HID_RS = (long)Bn * 32 * HWp;

    // ======== encoder layer 0 (hidden 1), compounding input attention ========
    for (int t = 0; t < Tn; t++) {
        const float* hp = (t == 0) ? h0 : hs0 + (long)(t - 1) * HWp;
        long hbs        = (t == 0) ? (long)HWp : (long)Tn * HWp;
        const float* cp = (t == 0) ? c0 : cs0 + (long)(t - 1) * HWp;
        long cbs = hbs;

        // attn conv1 (12->32, tanh) for all D features: tensor cores, 3xTF32
        mconv(32, 3,
              mkseg(xx, Tn, (long)Dn * HWp, (long)Tn * Dn * HWp, (long)HWp),
              mkseg(hp, 1, 0, hbs, 0),
              mkseg(cp, 1, 0, cbs, 0),
              wa1, 12, ba1, 1,
              hid, HID_RS, 32L * HWp, 12, 32, Dn);
        // attn conv2 (32->1) all features: FFMA
        conv(1, 0,
             mkseg(hid, 32, HWp, 32L * HWp, HID_RS), none, none,
             wa2, 32, ba2, nullptr, 0, 0, -1,
             score, (long)HWp, (long)Dn * HWp, 32, 1, Dn);
        inattn_k<<<(Bn * HWp + thr - 1) / thr, thr>>>(score, xx);

        // enc0 gate conv (11->4): tensor cores
        mconv(16, 3,
              mkseg(xx + (long)t * Dn * HWp, Dn, (long)HWp, (long)Tn * Dn * HWp, 0),
              mkseg(hp, 1, 0, hbs, 0), none,
              w_enc0, 11, b_enc0, 0,
              z, 0, 4L * HWp, 11, 4, 1);
        long n = (long)Bn * HWp;
        lstm_k<<<(n + thr - 1) / thr, thr>>>(z, cp, cbs,
                                             hs0 + (long)t * HWp, (long)Tn * HWp,
                                             cs0 + (long)t * HWp, (long)Tn * HWp,
                                             nullptr, 0, 1);
    }

    // ======== encoder layer 1 (65->256): tensor cores, 3xTF32 ========
    for (int t = 0; t < Tn; t++) {
        const float* hp = (t == 0) ? h1 : hs1 + (long)(t - 1) * 64 * HWp;
        long hbs        = (t == 0) ? 64L * HWp : (long)Tn * 64 * HWp;
        const float* cp = (t == 0) ? c1 : cs1 + (long)(t - 1) * 64 * HWp;

        mconv(64, 3,
              mkseg(hs0 + (long)t * HWp, 1, 0, (long)Tn * HWp, 0),
              mkseg(hp, 64, HWp, hbs, 0), none,
              w_enc1, 65, b_enc1, 0,
              z, 0, 256L * HWp, 65, 256, 1);
        long n = (long)Bn * 64 * HWp;
        lstm_k<<<(n + thr - 1) / thr, thr>>>(z, cp, hbs,
                                             hs1 + (long)t * 64 * HWp, (long)Tn * 64 * HWp,
                                             cs1 + (long)t * 64 * HWp, (long)Tn * 64 * HWp,
                                             nullptr, 0, 64);
    }

    // ======== temporal-attn h/c conv cache (128->32) all slots: tensor, 1xTF32 ========
    mconv(32, 1,
          mkseg(hs1, 64, HWp, (long)Tn * 64 * HWp, 64L * HWp),
          mkseg(cs1, 64, HWp, (long)Tn * 64 * HWp, 64L * HWp), none,
          wt1 + 9, 129, bt1, 0,
          tc, HID_RS, 32L * HWp, 128, 32, Tn);

    // ======== decoder ========
    float* out = (float*)d_out;
    for (int s = 0; s < 5; s++) {
        const float* yp; long ybs;
        if (s == 0) { yp = x + 90L * HWp; ybs = 100L * HWp; }
        else        { yp = hs0 + (long)(s - 1) * HWp; ybs = (long)Tn * HWp; }

        // hid[t] = tanh(conv_y(y) + tc[(s+t)%10]) : FFMA (tiny Cin=1)
        conv(8, 1,
             mkseg(yp, 1, 0, ybs, 0), none, none,
             wt1, 129, nullptr, tc, HID_RS, 32L * HWp, s,
             hid, HID_RS, 32L * HWp, 1, 32, Tn);
        conv(1, 0,
             mkseg(hid, 32, HWp, 32L * HWp, HID_RS), none, none,
             wt2, 32, bt2, nullptr, 0, 0, -1,
             score, (long)HWp, (long)Tn * HWp, 32, 1, Tn);
        tattn_k<<<(Bn * HWp + thr - 1) / thr, thr>>>(score, hs1, hatt, s);

        int pl = (s + 9) % Tn;

        // decoder L0 (65->256): tensor cores, 3xTF32
        mconv(64, 3,
              mkseg(yp, 1, 0, ybs, 0),
              mkseg(hatt, 64, HWp, 64L * HWp, 0), none,
              w_dec0, 65, b_dec0, 0,
              z, 0, 256L * HWp, 65, 256, 1);
        long n64 = (long)Bn * 64 * HWp;
        lstm_k<<<(n64 + thr - 1) / thr, thr>>>(z, cs1 + (long)pl * 64 * HWp, (long)Tn * 64 * HWp,
                                               hs1 + (long)s * 64 * HWp, (long)Tn * 64 * HWp,
                                               cs1 + (long)s * 64 * HWp, (long)Tn * 64 * HWp,
                                               nullptr, 0, 64);

        // refresh tc cache for slot s: tensor, 1xTF32
        mconv(32, 1,
              mkseg(hs1 + (long)s * 64 * HWp, 64, HWp, (long)Tn * 64 * HWp, 0),
              mkseg(cs1 + (long)s * 64 * HWp, 64, HWp, (long)Tn * 64 * HWp, 0), none,
              wt1 + 9, 129, bt1, 0,
              tc + (long)s * HID_RS, 0, 32L * HWp, 128, 32, 1);

        // decoder L1 (65->4): tensor cores
        mconv(16, 3,
              mkseg(hs1 + (long)s * 64 * HWp, 64, HWp, (long)Tn * 64 * HWp, 0),
              mkseg(hs0 + (long)pl * HWp, 1, 0, (long)Tn * HWp, 0), none,
              w_dec1, 65, b_dec1, 0,
              z, 0, 4L * HWp, 65, 4, 1);
        long n1 = (long)Bn * HWp;
        lstm_k<<<(n1 + thr - 1) / thr, thr>>>(z, cs0 + (long)pl * HWp, (long)Tn * HWp,
                                              hs0 + (long)s * HWp, (long)Tn * HWp,
                                              cs0 + (long)s * HWp, (long)Tn * HWp,
                                              out + (long)s * HWp, 5L * HWp, 1);
    }
}